// round 4
// baseline (speedup 1.0000x reference)
#include <cuda_runtime.h>
#include <cuda_fp16.h>
#include <cstdint>
#include <math.h>

// ---------------- scratch (no allocations allowed) ----------------
#define N_LEAVES_MAX 100000
#define MAXB 256
#define GRID_B 64

__device__ __align__(16) __half g_dleaf[N_LEAVES_MAX + 16];
__device__ int    g_maxint;          // max d as ordered int (positive floats)
__device__ float4 g_part[MAXB];      // (sum_exp, sum_sims_exp, sum_sims, -)

__device__ __forceinline__ void cp_async16(unsigned int dst_smem, const void* src) {
    asm volatile("cp.async.cg.shared.global [%0], [%1], 16;" :: "r"(dst_smem), "l"(src));
}

#define TILE_A 128
#define ROWF   132                       // padded row: 4-phase minimum, no conflicts
#define STAGE_B4 (TILE_A * (ROWF / 4) + TILE_A)   // float4s per stage (132/4=33)
#define STAGE_BYTES (TILE_A * ROWF * 4)           // 67584

// ---------------- Kernel A: persistent double-buffered leaf distances ----------------
__global__ __launch_bounds__(128) void leaf_dist_kernel(
        const int* __restrict__ lca,
        const float* __restrict__ emb,
        const float* __restrict__ leaves,
        const float* __restrict__ scale,
        int n_leaves)
{
    extern __shared__ float sm[];        // [2][TILE_A*ROWF]
    __shared__ __align__(16) float s_e[128];
    __shared__ float s_red[128];
    __shared__ float s_nx, s_inv;

    const int t       = threadIdx.x;
    const int n_tiles = (n_leaves + TILE_A - 1) / TILE_A;
    const int grid    = gridDim.x;
    const unsigned int sbase = (unsigned int)__cvta_generic_to_shared(sm);

    // my tiles: blockIdx.x + i*grid
    const int my_n = (n_tiles - blockIdx.x + grid - 1) / grid;

    // ---- issue prologue loads for tiles 0,1 (stages 0,1) ----
    #pragma unroll 1
    for (int p = 0; p < 2; p++) {
        int tile = blockIdx.x + p * grid;
        if (tile < n_tiles) {
            int leaf0 = tile * TILE_A;
            int valid = min(TILE_A, n_leaves - leaf0);
            const float4* src = reinterpret_cast<const float4*>(leaves) + (size_t)leaf0 * 32;
            unsigned int base = sbase + p * STAGE_BYTES;
            #pragma unroll
            for (int j = 0; j < 32; j++) {
                int f = t + j * 128;
                int row = f >> 5, col = f & 31;
                if (row < valid)
                    cp_async16(base + row * (ROWF * 4) + col * 16, src + f);
            }
        }
        asm volatile("cp.async.commit_group;");
    }

    // ---- build e1 while prologue loads fly ----
    const float* erow = emb + (long long)lca[0] * 128;
    float w = erow[t];
    s_red[t] = w * w;
    __syncthreads();
    for (int off = 64; off > 0; off >>= 1) {
        if (t < off) s_red[t] += s_red[t + off];
        __syncthreads();
    }
    if (t == 0) {
        float norm2  = s_red[0];
        float s      = fminf(fmaxf(scale[0], 0.01f), 1.0f - 0.001f);
        float factor = s / fmaxf(sqrtf(norm2), 1e-12f);
        float nx     = factor * factor * norm2;
        s_nx  = nx;
        s_inv = 1.0f / (1.0f - nx);
        s_red[0] = factor;
    }
    __syncthreads();
    s_e[t] = w * s_red[0];
    // s_e visible after the next __syncthreads below

    float dmax = 0.0f;
    const float4* er = reinterpret_cast<const float4*>(s_e);

    #pragma unroll 1
    for (int i = 0; i < my_n; i++) {
        asm volatile("cp.async.wait_group 1;");
        __syncthreads();

        const int tile  = blockIdx.x + i * grid;
        const int leaf0 = tile * TILE_A;
        const int valid = min(TILE_A, n_leaves - leaf0);
        const float* stg = sm + (i & 1) * (TILE_A * ROWF);

        if (t < valid) {
            const float4* yr = reinterpret_cast<const float4*>(stg + t * ROWF);
            float dot = 0.0f, ny = 0.0f;
            #pragma unroll
            for (int k = 0; k < 32; k++) {
                float4 y = yr[k];
                float4 e = er[k];      // broadcast
                dot = fmaf(e.x, y.x, fmaf(e.y, y.y, fmaf(e.z, y.z, fmaf(e.w, y.w, dot))));
                ny  = fmaf(y.x, y.x, fmaf(y.y, y.y, fmaf(y.z, y.z, fmaf(y.w, y.w, ny))));
            }
            float sq  = s_nx - 2.0f * dot + ny;
            float arg = 1.0f + 2.0f * sq * s_inv / (1.0f - ny);
            arg = fmaxf(arg, 1.0f + 1e-7f);
            float d = acoshf(arg);
            g_dleaf[leaf0 + t] = __float2half(d);
            dmax = fmaxf(dmax, d);
        }
        __syncthreads();               // stage fully consumed before refill

        // refill this stage with tile i+2
        {
            int tile2 = blockIdx.x + (i + 2) * grid;
            if (tile2 < n_tiles) {
                int l0 = tile2 * TILE_A;
                int v2 = min(TILE_A, n_leaves - l0);
                const float4* src = reinterpret_cast<const float4*>(leaves) + (size_t)l0 * 32;
                unsigned int base = sbase + (i & 1) * STAGE_BYTES;
                #pragma unroll
                for (int j = 0; j < 32; j++) {
                    int f = t + j * 128;
                    int row = f >> 5, col = f & 31;
                    if (row < v2)
                        cp_async16(base + row * (ROWF * 4) + col * 16, src + f);
                }
            }
            asm volatile("cp.async.commit_group;");
        }
    }

    // ---- block max -> global atomicMax (deterministic) ----
    s_red[t] = dmax;
    __syncthreads();
    for (int off = 64; off > 0; off >>= 1) {
        if (t < off) s_red[t] = fmaxf(s_red[t], s_red[t + off]);
        __syncthreads();
    }
    if (t == 0) atomicMax(&g_maxint, __float_as_int(s_red[0]));
}

// ---------------- Kernel B: branchless softmax partial sums ----------------
__global__ __launch_bounds__(1024) void pair_reduce_kernel(
        const int* __restrict__ l_idx,
        const int* __restrict__ r_idx,
        const float* __restrict__ sims,
        int n_pairs, int n_leaves)
{
    extern __shared__ __half s_tab[];
    __shared__ float r_se[1024], r_ss[1024], r_su[1024];

    const int t = threadIdx.x;

    // stage fp16 table (L2-resident) into smem
    unsigned int sb = (unsigned int)__cvta_generic_to_shared(s_tab);
    int nchunks = (n_leaves * 2 + 15) >> 4;
    const char* gsrc = reinterpret_cast<const char*>(g_dleaf);
    for (int c = t; c < nchunks; c += blockDim.x)
        cp_async16(sb + c * 16, gsrc + c * 16);
    asm volatile("cp.async.commit_group;");

    const float M = 40.0f * __int_as_float(g_maxint);

    asm volatile("cp.async.wait_group 0;");
    __syncthreads();

    float se = 0.0f, ss = 0.0f, su = 0.0f;

    const int n4 = n_pairs >> 2;
    const int4*   l4 = reinterpret_cast<const int4*>(l_idx);
    const int4*   r4 = reinterpret_cast<const int4*>(r_idx);
    const float4* s4 = reinterpret_cast<const float4*>(sims);
    const int stride = gridDim.x * blockDim.x;

    #pragma unroll 2
    for (int i = blockIdx.x * blockDim.x + t; i < n4; i += stride) {
        int4   li = l4[i];
        int4   ri = r4[i];
        float4 si = s4[i];
        float e0 = __expf(fmaf(20.0f, __half2float(s_tab[li.x]) + __half2float(s_tab[ri.x]), -M));
        float e1 = __expf(fmaf(20.0f, __half2float(s_tab[li.y]) + __half2float(s_tab[ri.y]), -M));
        float e2 = __expf(fmaf(20.0f, __half2float(s_tab[li.z]) + __half2float(s_tab[ri.z]), -M));
        float e3 = __expf(fmaf(20.0f, __half2float(s_tab[li.w]) + __half2float(s_tab[ri.w]), -M));
        se += (e0 + e1) + (e2 + e3);
        ss  = fmaf(si.x, e0, fmaf(si.y, e1, fmaf(si.z, e2, fmaf(si.w, e3, ss))));
        su += (si.x + si.y) + (si.z + si.w);
    }
    // scalar tail
    if (blockIdx.x == 0) {
        for (int i = n4 * 4 + t; i < n_pairs; i += blockDim.x) {
            float e = __expf(fmaf(20.0f,
                        __half2float(s_tab[l_idx[i]]) + __half2float(s_tab[r_idx[i]]), -M));
            float si = sims[i];
            se += e; ss = fmaf(si, e, ss); su += si;
        }
    }

    r_se[t] = se; r_ss[t] = ss; r_su[t] = su;
    __syncthreads();
    for (int off = 512; off > 0; off >>= 1) {
        if (t < off) {
            r_se[t] += r_se[t + off];
            r_ss[t] += r_ss[t + off];
            r_su[t] += r_su[t + off];
        }
        __syncthreads();
    }
    if (t == 0) g_part[blockIdx.x] = make_float4(r_se[0], r_ss[0], r_su[0], 0.0f);
}

// ---------------- Kernel C: finalize ----------------
__global__ void finalize_kernel(float* __restrict__ out, int nb)
{
    __shared__ float r_se[128], r_ss[128], r_su[128];
    const int t = threadIdx.x;
    float se = 0.0f, ss = 0.0f, su = 0.0f;
    for (int i = t; i < nb; i += 128) {
        float4 p = g_part[i];
        se += p.x; ss += p.y; su += p.z;
    }
    r_se[t] = se; r_ss[t] = ss; r_su[t] = su;
    __syncthreads();
    for (int off = 64; off > 0; off >>= 1) {
        if (t < off) {
            r_se[t] += r_se[t + off];
            r_ss[t] += r_ss[t + off];
            r_su[t] += r_su[t + off];
        }
        __syncthreads();
    }
    if (t == 0) out[0] = r_su[0] - r_ss[0] / r_se[0];
}

// ---------------- launch ----------------
extern "C" void kernel_launch(void* const* d_in, const int* in_sizes, int n_in,
                              void* d_out, int out_size)
{
    const int*   lca    = (const int*)  d_in[0];
    const int*   l_idx  = (const int*)  d_in[1];
    const int*   r_idx  = (const int*)  d_in[2];
    const float* sims   = (const float*)d_in[3];
    const float* emb    = (const float*)d_in[4];
    const float* leaves = (const float*)d_in[5];
    const float* scale  = (const float*)d_in[6];

    const int n_pairs  = in_sizes[1];
    const int n_leaves = in_sizes[5] / 128;

    const int smemA = 2 * STAGE_BYTES;                  // 135168
    cudaFuncSetAttribute(leaf_dist_kernel,
                         cudaFuncAttributeMaxDynamicSharedMemorySize, smemA);
    cudaFuncSetAttribute(pair_reduce_kernel,
                         cudaFuncAttributeMaxDynamicSharedMemorySize,
                         N_LEAVES_MAX * 2 + 64);
    const int smemB = ((n_leaves * 2 + 15) & ~15) + 32;

    int sm_count = 0;
    cudaDeviceGetAttribute(&sm_count, cudaDevAttrMultiProcessorCount, 0);
    if (sm_count <= 0 || sm_count > MAXB) sm_count = 148;

    leaf_dist_kernel<<<sm_count, 128, smemA>>>(lca, emb, leaves, scale, n_leaves);
    pair_reduce_kernel<<<GRID_B, 1024, smemB>>>(l_idx, r_idx, sims, n_pairs, n_leaves);
    finalize_kernel<<<1, 128>>>((float*)d_out, GRID_B);
}